// round 15
// baseline (speedup 1.0000x reference)
#include <cuda_runtime.h>
#include <cuda_bf16.h>
#include <cstdint>
#include <math.h>

#define TS 63
#define B 32
#define S 256
#define H 512
#define V 32000
#define NG (V/16)              /* 2000 gen A-row groups */
#define KC (H/16)              /* 32 bf16 k-chunks */
#define XFRAG (4*KC*32*4)      /* bf16 X image: uint32 count */
#define GENB 250               /* V/128 generator tiles */
#define NBLK 148               /* persistent blocks (<= SM count) */

// ------------------------- device scratch -----------------------------------
__device__ float g_h0[B*H];
__device__ float g_h1[B*H];
__device__ float g_c[2][B*H];
__device__ float g_emb[TS][B*H];
__device__ float g_dec[B*H];
__device__ float g_part0[3][2048*B];
__device__ float g_part1[2][2048*B];
__device__ float g_WaT[H*H];
__device__ float g_sumZ[TS*B];
__device__ __align__(16) uint32_t g_Wq[(size_t)NG*KC*32*8];
__device__ __align__(16) uint32_t g_xq[XFRAG];
__device__ unsigned int g_barArrive;
__device__ volatile unsigned int g_barGen;

// ------------------------- helpers -------------------------------------------
__device__ __forceinline__ void mma16816(float c[4], const uint32_t a[4],
                                         uint32_t b0, uint32_t b1) {
    asm volatile("mma.sync.aligned.m16n8k16.row.col.f32.bf16.bf16.f32 "
        "{%0,%1,%2,%3}, {%4,%5,%6,%7}, {%8,%9}, {%0,%1,%2,%3};"
        : "+f"(c[0]), "+f"(c[1]), "+f"(c[2]), "+f"(c[3])
        : "r"(a[0]), "r"(a[1]), "r"(a[2]), "r"(a[3]), "r"(b0), "r"(b1));
}
__device__ __forceinline__ uint32_t pack_bf16(float x, float y) {
    __nv_bfloat162 v = __floats2bfloat162_rn(x, y);
    return *reinterpret_cast<uint32_t*>(&v);
}
__device__ __forceinline__ float bf16_hi_f(float x) {
    __nv_bfloat16 h = __float2bfloat16_rn(x);
    return __bfloat162float(h);
}
__device__ __forceinline__ void scatter_frag(uint32_t* base, int b, int k, float v) {
    int bg = b >> 3, gid = b & 7;
    int c = k >> 4, kk = k & 15;
    int hi8 = kk >> 3, tig = (kk >> 1) & 3, half = kk & 1;
    int lane = gid*4 + tig;
    int idx2 = (bg*KC + c)*32 + lane;
    __nv_bfloat16 hb = __float2bfloat16_rn(v);
    float hv = __bfloat162float(hb);
    __nv_bfloat16 lb = __float2bfloat16_rn(v - hv);
    unsigned short* p16 = reinterpret_cast<unsigned short*>(base);
    p16[(idx2*4 + hi8)*2 + half]     = *reinterpret_cast<unsigned short*>(&hb);
    p16[(idx2*4 + 2 + hi8)*2 + half] = *reinterpret_cast<unsigned short*>(&lb);
}
__device__ __forceinline__ float sigm(float x) { return 1.f/(1.f+expf(-x)); }

// grid-wide barrier (sense-reversing, generation counter)
__device__ __forceinline__ void gsync() {
    __syncthreads();
    if (threadIdx.x == 0) {
        unsigned int gen = g_barGen;
        __threadfence();
        if (atomicAdd(&g_barArrive, 1u) == NBLK - 1u) {
            g_barArrive = 0u;
            __threadfence();
            g_barGen = gen + 1u;
        } else {
            while (g_barGen == gen) __nanosleep(64);
        }
        __threadfence();
    }
    __syncthreads();
}

// warp GEMV with L2-coherent X loads (cross-block data)
__device__ __forceinline__ void warp_gemv_cg(const float* __restrict__ Wrow,
                                             const float* __restrict__ X,
                                             float acc[B]) {
    const int lane = threadIdx.x & 31;
#pragma unroll
    for (int kk = 0; kk < 4; kk++) {
        const int k = kk*128 + lane*4;
        const float4 w = *reinterpret_cast<const float4*>(Wrow + k);
#pragma unroll
        for (int b = 0; b < B; b++) {
            const float4 x = __ldcg(reinterpret_cast<const float4*>(X + b*H + k));
            acc[b] += w.x*x.x + w.y*x.y + w.z*x.z + w.w*x.w;
        }
    }
}
__device__ __forceinline__ float warp_reduce_b(float acc[B], float* sm) {
    const int lane = threadIdx.x & 31;
#pragma unroll
    for (int b = 0; b < B; b++) sm[b*33 + lane] = acc[b];
    __syncwarp();
    float s = 0.f;
#pragma unroll
    for (int j = 0; j < 32; j++) s += sm[lane*33 + j];
    return s;
}

// ------------------------- shared union --------------------------------------
union LoopSmem {
    float gemv[8][33*32];                              // 33792 B
    float Dsm[128*33];                                 // 16896 B
    struct { float sh1[H], sq[H], al[S], red[256], sctx[H]; } at;  // 8192 B
};

// ------------------------- generator tile (bf16x3, proven) -------------------
__device__ void gen_tile(int tile, int tGen, const float* __restrict__ bgen,
                         float* __restrict__ out, float* Dsm) {
    const int tid = threadIdx.x;
    const int wid = tid >> 5, lane = tid & 31;
    const int gid = lane >> 2, tig = lane & 3;
    const int nt = tile * 128;
    const int ngrp = tile*8 + wid;
    const uint32_t* wq = g_Wq + (size_t)ngrp*KC*32*8;

    float acc[4][4] = {};
    for (int c = 0; c < KC; c++) {
        const uint32_t* ap = wq + (c*32 + lane)*8;
        uint4 ahiv = *reinterpret_cast<const uint4*>(ap);
        uint4 alov = *reinterpret_cast<const uint4*>(ap + 4);
        uint32_t ahi[4] = {ahiv.x, ahiv.y, ahiv.z, ahiv.w};
        uint32_t alo[4] = {alov.x, alov.y, alov.z, alov.w};
#pragma unroll
        for (int bg = 0; bg < 4; bg++) {
            uint4 xb = __ldcg(reinterpret_cast<const uint4*>(&g_xq[((bg*KC + c)*32 + lane)*4]));
            mma16816(acc[bg], ahi, xb.x, xb.y);
            mma16816(acc[bg], ahi, xb.z, xb.w);
            mma16816(acc[bg], alo, xb.x, xb.y);
        }
    }
#pragma unroll
    for (int bg = 0; bg < 4; bg++) {
#pragma unroll
        for (int r = 0; r < 4; r++) {
            int nl = wid*16 + gid + ((r >= 2) ? 8 : 0);
            int b  = bg*8 + tig*2 + (r & 1);
            Dsm[nl*33 + b] = acc[bg][r];
        }
    }
    __syncthreads();

    const int n = tid & 127, bh = tid >> 7;
    const float bias = bgen[nt + n];
    float* obase = out + (size_t)tGen*B*V + nt + n;
#pragma unroll
    for (int j = 0; j < 16; j++) {
        int b = bh*16 + j;
        float v = Dsm[n*33 + b] + bias;
        obase[(size_t)b*V] = v;
        Dsm[n*33 + b] = expf(v);
    }
    __syncthreads();
    if (tid < 32) {
        float s = 0.f;
#pragma unroll 8
        for (int nn = 0; nn < 128; nn++) s += Dsm[nn*33 + tid];
        atomicAdd(&g_sumZ[tGen*B + tid], s);
    }
}

// ------------------------- prologue/epilogue kernels --------------------------
__global__ void __launch_bounds__(256) k_init(const float* __restrict__ eh,
                                              const float* __restrict__ ec,
                                              const float* __restrict__ Wa) {
    int idx = blockIdx.x*256 + threadIdx.x;           // grid covers H*H
    if (idx < 2*B*H) {
        (&g_c[0][0])[idx] = ec[idx];
        int layer = idx >> 14;
        int rem = idx & (B*H - 1);
        if (layer == 0) g_h0[rem] = eh[idx];
        else            g_h1[rem] = eh[idx];
    }
    if (idx < B*H)   g_dec[idx] = 0.f;
    if (idx < TS*B)  g_sumZ[idx] = 0.f;
    if (idx < H*H)   { int h = idx / H; int k = idx - h*H; g_WaT[k*H + h] = Wa[idx]; }
}

__global__ void __launch_bounds__(256) k_embed(const int* __restrict__ tgt,
                                               const float* __restrict__ et) {
    int idx = blockIdx.x*256 + threadIdx.x;           // < TS*B*H
    int e = idx & (H - 1);
    int r = idx >> 9;
    int tok = tgt[r];
    (&g_emb[0][0])[idx] = et[(size_t)tok*H + e];
}

__global__ void __launch_bounds__(256) k_pack(const float* __restrict__ Wgen) {
    int idx = blockIdx.x*256 + threadIdx.x;           // < NG*KC*32*8
    int reg  = idx & 7;
    int lane = (idx >> 3) & 31;
    int c    = (idx >> 8) & 31;
    int g    = idx >> 13;
    int split = reg >> 2, r4 = reg & 3;
    int gid = lane >> 2, tig = lane & 3;
    int n = g*16 + gid + ((r4 & 1) ? 8 : 0);
    int k = c*16 + tig*2 + ((r4 & 2) ? 8 : 0);
    float w0 = Wgen[(size_t)n*H + k];
    float w1 = Wgen[(size_t)n*H + k + 1];
    float h0 = bf16_hi_f(w0), h1 = bf16_hi_f(w1);
    g_Wq[idx] = (split == 0) ? pack_bf16(h0, h1) : pack_bf16(w0 - h0, w1 - h1);
}

__global__ void __launch_bounds__(256) k_lsm(float* __restrict__ out) {
    __shared__ float lz;
    const int t = blockIdx.z, b = blockIdx.y;
    if (threadIdx.x == 0) lz = logf(g_sumZ[t*B + b]);
    __syncthreads();
    int v = blockIdx.x*256 + threadIdx.x;
    out[((size_t)(t*B + b))*V + v] -= lz;
}

// ------------------------- THE persistent loop kernel -------------------------
__global__ void __launch_bounds__(256) k_loop(const float* __restrict__ Wx0,
                                              const float* __restrict__ Wh0,
                                              const float* __restrict__ Wh1,
                                              const float* __restrict__ Wx1,
                                              const float* __restrict__ b0v,
                                              const float* __restrict__ b1v,
                                              const float* __restrict__ mb,
                                              const int*   __restrict__ mlen,
                                              const float* __restrict__ Wc,
                                              const float* __restrict__ bgen,
                                              float* __restrict__ out,
                                              float* __restrict__ attn_out) {
    __shared__ LoopSmem u;
    const int bid = blockIdx.x;
    const int tid = threadIdx.x;
    const int warp = tid >> 5, lane = tid & 31;

    for (int t = 0; t < TS; t++) {
        // ---- Phase A: gen(t-1) [0,250) + 4 gate GEMVs [250,1274) ----
        for (int job = bid; job < GENB + 1024; job += NBLK) {
            __syncthreads();
            if (job < GENB) {
                if (t > 0) gen_tile(job, t - 1, bgen, out, u.Dsm);
            } else {
                const int gj = job - GENB;
                const int p = gj >> 8, nb = gj & 255;
                const int n = nb*8 + warp;
                const float* Wrow; const float* X; float* dst;
                if (p == 0)      { Wrow = Wx0 + (size_t)n*1024;       X = g_emb[t]; dst = &g_part0[0][0]; }
                else if (p == 1) { Wrow = Wx0 + (size_t)n*1024 + 512; X = g_dec;    dst = &g_part0[1][0]; }
                else if (p == 2) { Wrow = Wh0 + (size_t)n*512;        X = g_h0;     dst = &g_part0[2][0]; }
                else             { Wrow = Wh1 + (size_t)n*512;        X = g_h1;     dst = &g_part1[1][0]; }
                float acc[B] = {};
                warp_gemv_cg(Wrow, X, acc);
                float s = warp_reduce_b(acc, u.gemv[warp]);
                dst[n*B + lane] = s;
            }
        }
        gsync();

        // ---- Phase B: act0 (64 jobs x 256 elems) ----
        for (int job = bid; job < 64; job += NBLK) {
            int idx = job*256 + tid;
            int b = idx & 31, j = idx >> 5;
            float gi = b0v[j], gf = b0v[512+j], gg = b0v[1024+j], go = b0v[1536+j];
#pragma unroll
            for (int p = 0; p < 3; p++) {
                const float* pp = &g_part0[p][0];
                gi += __ldcg(pp + (j       )*B + b);
                gf += __ldcg(pp + (512 + j )*B + b);
                gg += __ldcg(pp + (1024 + j)*B + b);
                go += __ldcg(pp + (1536 + j)*B + b);
            }
            float c  = g_c[0][b*H + j];
            float cn = sigm(gf)*c + sigm(gi)*tanhf(gg);
            g_c[0][b*H + j] = cn;
            g_h0[b*H + j] = sigm(go)*tanhf(cn);
        }
        gsync();

        // ---- Phase C: Wx1 x h0 -> part1[0] (256 jobs x 8 warps) ----
        for (int job = bid; job < 256; job += NBLK) {
            __syncthreads();
            const int n = job*8 + warp;
            float acc[B] = {};
            warp_gemv_cg(Wx1 + (size_t)n*512, g_h0, acc);
            float s = warp_reduce_b(acc, u.gemv[warp]);
            g_part1[0][n*B + lane] = s;
        }
        gsync();

        // ---- Phase D: act1 + q + attention + context + Wc (32 jobs) ----
        for (int b = bid; b < B; b += NBLK) {
            __syncthreads();
            const int len = mlen[b];
            for (int j = tid; j < H; j += 256) {
                float gi = b1v[j], gf = b1v[512+j], gg = b1v[1024+j], go = b1v[1536+j];
#pragma unroll
                for (int p = 0; p < 2; p++) {
                    const float* pp = &g_part1[p][0];
                    gi += __ldcg(pp + (j       )*B + b);
                    gf += __ldcg(pp + (512 + j )*B + b);
                    gg += __ldcg(pp + (1024 + j)*B + b);
                    go += __ldcg(pp + (1536 + j)*B + b);
                }
                float c  = g_c[1][b*H + j];
                float cn = sigm(gf)*c + sigm(gi)*tanhf(gg);
                g_c[1][b*H + j] = cn;
                float hn = sigm(go)*tanhf(cn);
                g_h1[b*H + j] = hn;
                u.at.sh1[j] = hn;
            }
            __syncthreads();

            for (int n0 = warp; n0 < H; n0 += 8) {
                const float* wr = g_WaT + (size_t)n0*H;
                float a = 0.f;
#pragma unroll
                for (int kk = 0; kk < 4; kk++) {
                    int k = kk*128 + lane*4;
                    float4 w  = *reinterpret_cast<const float4*>(wr + k);
                    float4 hx = *reinterpret_cast<const float4*>(u.at.sh1 + k);
                    a += w.x*hx.x + w.y*hx.y + w.z*hx.z + w.w*hx.w;
                }
#pragma unroll
                for (int off = 16; off; off >>= 1) a += __shfl_xor_sync(0xffffffffu, a, off);
                if (lane == 0) u.at.sq[n0] = a;
            }
            __syncthreads();

            for (int s0 = warp; s0 < S; s0 += 8) {
                const float* m = mb + ((size_t)s0*B + b)*H;
                float a = 0.f;
#pragma unroll
                for (int kk = 0; kk < 4; kk++) {
                    int k = kk*128 + lane*4;
                    float4 mv = *reinterpret_cast<const float4*>(m + k);
                    float4 qv = *reinterpret_cast<const float4*>(u.at.sq + k);
                    a += mv.x*qv.x + mv.y*qv.y + mv.z*qv.z + mv.w*qv.w;
                }
#pragma unroll
                for (int off = 16; off; off >>= 1) a += __shfl_xor_sync(0xffffffffu, a, off);
                if (lane == 0) u.at.al[s0] = (s0 < len) ? a : -1.0e9f;
            }
            __syncthreads();

            float v = u.at.al[tid];
            u.at.red[tid] = v; __syncthreads();
            for (int o = 128; o; o >>= 1) { if (tid < o) u.at.red[tid] = fmaxf(u.at.red[tid], u.at.red[tid+o]); __syncthreads(); }
            float vmax = u.at.red[0];
            __syncthreads();
            float e = expf(v - vmax);
            u.at.red[tid] = e; __syncthreads();
            for (int o = 128; o; o >>= 1) { if (tid < o) u.at.red[tid] += u.at.red[tid+o]; __syncthreads(); }
            float p = e / u.at.red[0];
            u.at.al[tid] = p;
            attn_out[((size_t)t*B + b)*S + tid] = p;
            __syncthreads();

            for (int k = tid; k < H; k += 256) {
                float acc = 0.f;
#pragma unroll 4
                for (int s = 0; s < S; s++) acc += u.at.al[s] * mb[((size_t)s*B + b)*H + k];
                u.at.sctx[k] = acc;
            }
            __syncthreads();

            // fused Wc: warp per output row n
            for (int n = warp; n < H; n += 8) {
                const float* wr = Wc + (size_t)n*1024;
                float a = 0.f;
#pragma unroll
                for (int kk = 0; kk < 4; kk++) {
                    int k = kk*128 + lane*4;
                    float4 w  = *reinterpret_cast<const float4*>(wr + k);
                    float4 cx = *reinterpret_cast<const float4*>(u.at.sctx + k);
                    a += w.x*cx.x + w.y*cx.y + w.z*cx.z + w.w*cx.w;
                    float4 w2 = *reinterpret_cast<const float4*>(wr + 512 + k);
                    float4 hx = *reinterpret_cast<const float4*>(u.at.sh1 + k);
                    a += w2.x*hx.x + w2.y*hx.y + w2.z*hx.z + w2.w*hx.w;
                }
#pragma unroll
                for (int off = 16; off; off >>= 1) a += __shfl_xor_sync(0xffffffffu, a, off);
                if (lane == 0) {
                    float d = tanhf(a);
                    g_dec[b*H + n] = d;
                    scatter_frag(g_xq, b, n, d);
                }
            }
        }
        gsync();
    }

    // ---- final generator (t = TS-1) ----
    for (int job = bid; job < GENB; job += NBLK) {
        __syncthreads();
        gen_tile(job, TS - 1, bgen, out, u.Dsm);
    }
}

// ------------------------- launch -------------------------------------------
extern "C" void kernel_launch(void* const* d_in, const int* in_sizes, int n_in,
                              void* d_out, int out_size) {
    const int*   tgt   = (const int*)  d_in[0];
    const float* mb    = (const float*)d_in[1];
    const int*   mlen  = (const int*)  d_in[2];
    const float* enc_h = (const float*)d_in[3];
    const float* enc_c = (const float*)d_in[4];
    const float* emb   = (const float*)d_in[5];
    const float* Wx0   = (const float*)d_in[6];
    const float* Wh0   = (const float*)d_in[7];
    const float* b0    = (const float*)d_in[8];
    const float* Wx1   = (const float*)d_in[9];
    const float* Wh1   = (const float*)d_in[10];
    const float* b1    = (const float*)d_in[11];
    const float* Wa    = (const float*)d_in[12];
    const float* Wc    = (const float*)d_in[13];
    const float* Wgen  = (const float*)d_in[14];
    const float* bgen  = (const float*)d_in[15];

    float* out      = (float*)d_out;
    float* attn_out = out + (size_t)TS*B*V;

    k_init <<<(H*H + 255)/256, 256>>>(enc_h, enc_c, Wa);
    k_embed<<<(TS*B*H)/256, 256>>>(tgt, emb);
    k_pack <<<NG*32, 256>>>(Wgen);

    k_loop<<<NBLK, 256>>>(Wx0, Wh0, Wh1, Wx1, b0, b1, mb, mlen, Wc, bgen,
                          out, attn_out);

    k_lsm<<<dim3(V/256, B, TS), 256>>>(out);
}

// round 16
// speedup vs baseline: 1.1551x; 1.1551x over previous
#include <cuda_runtime.h>
#include <cuda_bf16.h>
#include <cstdint>
#include <math.h>

#define TS 63
#define B 32
#define S 256
#define H 512
#define V 32000
#define NG (V/16)              /* 2000 gen A-row groups */
#define KC (H/16)              /* 32 bf16 k-chunks */
#define XFRAG (4*KC*32*4)      /* bf16 X image: uint32 count */
#define GENB 250               /* V/128 generator tiles */
#define GATEB 1024             /* gate GEMV blocks */
#define ACT0B 64               /* act0 blocks */
#define G1B 256                /* g1p0 blocks */
#define MIXB (GENB + GATEB + ACT0B + G1B)   /* 1594 */

// ------------------------- device scratch -----------------------------------
__device__ float g_h0[B*H];
__device__ float g_h1[B*H];
__device__ float g_c[2][B*H];
__device__ float g_emb[TS][B*H];
__device__ float g_dec[B*H];
__device__ float g_part0[3][2048*B];
__device__ float g_part1[2][2048*B];
__device__ float g_WaT[H*H];
__device__ float g_sumZ[TS*B];
__device__ __align__(16) uint32_t g_Wq[(size_t)NG*KC*32*8];
__device__ __align__(16) uint32_t g_xq[XFRAG];
__device__ volatile unsigned int g_cnt0;   // gate blocks done
__device__ volatile unsigned int g_cnt1;   // act0 blocks done

// ------------------------- helpers -------------------------------------------
__device__ __forceinline__ void mma16816(float c[4], const uint32_t a[4],
                                         uint32_t b0, uint32_t b1) {
    asm volatile("mma.sync.aligned.m16n8k16.row.col.f32.bf16.bf16.f32 "
        "{%0,%1,%2,%3}, {%4,%5,%6,%7}, {%8,%9}, {%0,%1,%2,%3};"
        : "+f"(c[0]), "+f"(c[1]), "+f"(c[2]), "+f"(c[3])
        : "r"(a[0]), "r"(a[1]), "r"(a[2]), "r"(a[3]), "r"(b0), "r"(b1));
}
__device__ __forceinline__ uint32_t pack_bf16(float x, float y) {
    __nv_bfloat162 v = __floats2bfloat162_rn(x, y);
    return *reinterpret_cast<uint32_t*>(&v);
}
__device__ __forceinline__ float bf16_hi_f(float x) {
    __nv_bfloat16 h = __float2bfloat16_rn(x);
    return __bfloat162float(h);
}
__device__ __forceinline__ void scatter_frag(uint32_t* base, int b, int k, float v) {
    int bg = b >> 3, gid = b & 7;
    int c = k >> 4, kk = k & 15;
    int hi8 = kk >> 3, tig = (kk >> 1) & 3, half = kk & 1;
    int lane = gid*4 + tig;
    int idx2 = (bg*KC + c)*32 + lane;
    __nv_bfloat16 hb = __float2bfloat16_rn(v);
    float hv = __bfloat162float(hb);
    __nv_bfloat16 lb = __float2bfloat16_rn(v - hv);
    unsigned short* p16 = reinterpret_cast<unsigned short*>(base);
    p16[(idx2*4 + hi8)*2 + half]     = *reinterpret_cast<unsigned short*>(&hb);
    p16[(idx2*4 + 2 + hi8)*2 + half] = *reinterpret_cast<unsigned short*>(&lb);
}
__device__ __forceinline__ float sigm(float x) { return 1.f/(1.f+expf(-x)); }

// producer epilogue: all threads fence, then one thread counts
__device__ __forceinline__ void block_signal(volatile unsigned int* cnt) {
    __threadfence();
    __syncthreads();
    if (threadIdx.x == 0) atomicAdd((unsigned int*)cnt, 1u);
}
// consumer prologue: spin until counter reaches target
__device__ __forceinline__ void block_wait(volatile unsigned int* cnt, unsigned int target) {
    if (threadIdx.x == 0) {
        while (*cnt < target) __nanosleep(64);
        __threadfence();
    }
    __syncthreads();
}

// warp GEMV; cg=true uses L2-coherent X loads (same-launch cross-SM data)
template <bool CG>
__device__ __forceinline__ void warp_gemv_acc(const float* __restrict__ Wrow,
                                              const float* __restrict__ X,
                                              float acc[B]) {
    const int lane = threadIdx.x & 31;
#pragma unroll
    for (int kk = 0; kk < 4; kk++) {
        const int k = kk*128 + lane*4;
        const float4 w = *reinterpret_cast<const float4*>(Wrow + k);
#pragma unroll
        for (int b = 0; b < B; b++) {
            float4 x;
            if (CG) x = __ldcg(reinterpret_cast<const float4*>(X + b*H + k));
            else    x = *reinterpret_cast<const float4*>(X + b*H + k);
            acc[b] += w.x*x.x + w.y*x.y + w.z*x.z + w.w*x.w;
        }
    }
}
__device__ __forceinline__ float warp_reduce_b(float acc[B], float* sm) {
    const int lane = threadIdx.x & 31;
#pragma unroll
    for (int b = 0; b < B; b++) sm[b*33 + lane] = acc[b];
    __syncwarp();
    float s = 0.f;
#pragma unroll
    for (int j = 0; j < 32; j++) s += sm[lane*33 + j];
    return s;
}

// ------------------------- generator tile (bf16x3, proven) -------------------
__device__ void gen_tile(int tile, int tGen, const float* __restrict__ bgen,
                         float* __restrict__ out, float* Dsm) {
    const int tid = threadIdx.x;
    const int wid = tid >> 5, lane = tid & 31;
    const int gid = lane >> 2, tig = lane & 3;
    const int nt = tile * 128;
    const int ngrp = tile*8 + wid;
    const uint32_t* wq = g_Wq + (size_t)ngrp*KC*32*8;

    float acc[4][4] = {};
    for (int c = 0; c < KC; c++) {
        const uint32_t* ap = wq + (c*32 + lane)*8;
        uint4 ahiv = *reinterpret_cast<const uint4*>(ap);
        uint4 alov = *reinterpret_cast<const uint4*>(ap + 4);
        uint32_t ahi[4] = {ahiv.x, ahiv.y, ahiv.z, ahiv.w};
        uint32_t alo[4] = {alov.x, alov.y, alov.z, alov.w};
#pragma unroll
        for (int bg = 0; bg < 4; bg++) {
            uint4 xb = *reinterpret_cast<const uint4*>(&g_xq[((bg*KC + c)*32 + lane)*4]);
            mma16816(acc[bg], ahi, xb.x, xb.y);
            mma16816(acc[bg], ahi, xb.z, xb.w);
            mma16816(acc[bg], alo, xb.x, xb.y);
        }
    }
#pragma unroll
    for (int bg = 0; bg < 4; bg++) {
#pragma unroll
        for (int r = 0; r < 4; r++) {
            int nl = wid*16 + gid + ((r >= 2) ? 8 : 0);
            int b  = bg*8 + tig*2 + (r & 1);
            Dsm[nl*33 + b] = acc[bg][r];
        }
    }
    __syncthreads();

    const int n = tid & 127, bh = tid >> 7;
    const float bias = bgen[nt + n];
    float* obase = out + (size_t)tGen*B*V + nt + n;
#pragma unroll
    for (int j = 0; j < 16; j++) {
        int b = bh*16 + j;
        float v = Dsm[n*33 + b] + bias;
        obase[(size_t)b*V] = v;
        Dsm[n*33 + b] = expf(v);
    }
    __syncthreads();
    if (tid < 32) {
        float s = 0.f;
#pragma unroll 8
        for (int nn = 0; nn < 128; nn++) s += Dsm[nn*33 + tid];
        atomicAdd(&g_sumZ[tGen*B + tid], s);
    }
}

// ------------------------- prologue kernels -----------------------------------
__global__ void __launch_bounds__(256) k_init(const float* __restrict__ eh,
                                              const float* __restrict__ ec,
                                              const float* __restrict__ Wa) {
    int idx = blockIdx.x*256 + threadIdx.x;           // grid covers H*H
    if (idx == 0) { g_cnt0 = 0u; g_cnt1 = 0u; }
    if (idx < 2*B*H) {
        (&g_c[0][0])[idx] = ec[idx];
        int layer = idx >> 14;
        int rem = idx & (B*H - 1);
        if (layer == 0) g_h0[rem] = eh[idx];
        else            g_h1[rem] = eh[idx];
    }
    if (idx < B*H)   g_dec[idx] = 0.f;
    if (idx < TS*B)  g_sumZ[idx] = 0.f;
    if (idx < H*H)   { int h = idx / H; int k = idx - h*H; g_WaT[k*H + h] = Wa[idx]; }
}

__global__ void __launch_bounds__(256) k_embed(const int* __restrict__ tgt,
                                               const float* __restrict__ et) {
    int idx = blockIdx.x*256 + threadIdx.x;           // < TS*B*H
    int e = idx & (H - 1);
    int r = idx >> 9;
    int tok = tgt[r];
    (&g_emb[0][0])[idx] = et[(size_t)tok*H + e];
}

__global__ void __launch_bounds__(256) k_pack(const float* __restrict__ Wgen) {
    int idx = blockIdx.x*256 + threadIdx.x;           // < NG*KC*32*8
    int reg  = idx & 7;
    int lane = (idx >> 3) & 31;
    int c    = (idx >> 8) & 31;
    int g    = idx >> 13;
    int split = reg >> 2, r4 = reg & 3;
    int gid = lane >> 2, tig = lane & 3;
    int n = g*16 + gid + ((r4 & 1) ? 8 : 0);
    int k = c*16 + tig*2 + ((r4 & 2) ? 8 : 0);
    float w0 = Wgen[(size_t)n*H + k];
    float w1 = Wgen[(size_t)n*H + k + 1];
    float h0 = bf16_hi_f(w0), h1 = bf16_hi_f(w1);
    g_Wq[idx] = (split == 0) ? pack_bf16(h0, h1) : pack_bf16(w0 - h0, w1 - h1);
}

// ------------------------- k_mix: gen + gates + act0 + g1p0 -------------------
// bids [0,250): gen(t-1). [250,1274): gates -> cnt0. [1274,1338): act0 (waits
// cnt0 == (t+1)*1024) -> cnt1. [1338,1594): g1p0 (waits cnt1 == (t+1)*64).
__global__ void __launch_bounds__(256) k_mix(const float* __restrict__ Wx0,
                                             const float* __restrict__ Wh0,
                                             const float* __restrict__ Wh1,
                                             const float* __restrict__ Wx1,
                                             const float* __restrict__ b0v,
                                             const float* __restrict__ bgen,
                                             float* __restrict__ out,
                                             int t, int tGen) {
    __shared__ float sm[8][33*32];                    // gemv scratch / Dsm alias
    const int bid = blockIdx.x;
    const int warp = threadIdx.x >> 5, lane = threadIdx.x & 31;
    const int tid = threadIdx.x;

    if (bid < GENB) {
        if (tGen >= 0) gen_tile(bid, tGen, bgen, out, &sm[0][0]);
        return;
    }
    if (bid < GENB + GATEB) {
        const int gj = bid - GENB;                    // 0..1023
        const int p = gj >> 8, nb = gj & 255;
        const int n = nb*8 + warp;                    // 0..2047
        const float* Wrow; const float* X; float* dst;
        if (p == 0)      { Wrow = Wx0 + (size_t)n*1024;       X = g_emb[t]; dst = &g_part0[0][0]; }
        else if (p == 1) { Wrow = Wx0 + (size_t)n*1024 + 512; X = g_dec;    dst = &g_part0[1][0]; }
        else if (p == 2) { Wrow = Wh0 + (size_t)n*512;        X = g_h0;     dst = &g_part0[2][0]; }
        else             { Wrow = Wh1 + (size_t)n*512;        X = g_h1;     dst = &g_part1[1][0]; }
        float acc[B] = {};
        warp_gemv_acc<false>(Wrow, X, acc);           // cross-launch inputs
        float s = warp_reduce_b(acc, sm[warp]);
        dst[n*B + lane] = s;
        block_signal(&g_cnt0);
        return;
    }
    if (bid < GENB + GATEB + ACT0B) {
        block_wait(&g_cnt0, (unsigned int)(t + 1)*GATEB);
        const int job = bid - (GENB + GATEB);         // 0..63
        int idx = job*256 + tid;
        int b = idx & 31, j = idx >> 5;
        float gi = b0v[j], gf = b0v[512+j], gg = b0v[1024+j], go = b0v[1536+j];
#pragma unroll
        for (int p = 0; p < 3; p++) {
            const float* pp = &g_part0[p][0];
            gi += __ldcg(pp + (j       )*B + b);
            gf += __ldcg(pp + (512 + j )*B + b);
            gg += __ldcg(pp + (1024 + j)*B + b);
            go += __ldcg(pp + (1536 + j)*B + b);
        }
        float c  = g_c[0][b*H + j];
        float cn = sigm(gf)*c + sigm(gi)*tanhf(gg);
        g_c[0][b*H + j] = cn;
        g_h0[b*H + j] = sigm(go)*tanhf(cn);
        block_signal(&g_cnt1);
        return;
    }
    // g1p0: Wx1 x h0_new -> part1[0]
    block_wait(&g_cnt1, (unsigned int)(t + 1)*ACT0B);
    const int n = (bid - (GENB + GATEB + ACT0B))*8 + warp;   // 0..2047
    float acc[B] = {};
    warp_gemv_acc<true>(Wx1 + (size_t)n*512, g_h0, acc);     // same-launch h0
    float s = warp_reduce_b(acc, sm[warp]);
    g_part1[0][n*B + lane] = s;
}

// ------------------------- k_attn: act1 + q + attention + ctx + Wc -----------
__global__ void __launch_bounds__(256) k_attn(const float* __restrict__ mb,
                                              const int* __restrict__ mlen,
                                              const float* __restrict__ b1v,
                                              const float* __restrict__ Wc,
                                              float* __restrict__ attn_out, int t) {
    __shared__ float sh1[H];
    __shared__ float sq[H];
    __shared__ float al[S];
    __shared__ float red[256];
    __shared__ float sctx[H];
    const int b = blockIdx.x;
    const int tid = threadIdx.x, warp = tid >> 5, lane = tid & 31;
    const int len = mlen[b];

    for (int j = tid; j < H; j += 256) {
        float gi = b1v[j], gf = b1v[512+j], gg = b1v[1024+j], go = b1v[1536+j];
#pragma unroll
        for (int p = 0; p < 2; p++) {
            const float* pp = &g_part1[p][0];
            gi += pp[(j       )*B + b];
            gf += pp[(512 + j )*B + b];
            gg += pp[(1024 + j)*B + b];
            go += pp[(1536 + j)*B + b];
        }
        float c  = g_c[1][b*H + j];
        float cn = sigm(gf)*c + sigm(gi)*tanhf(gg);
        g_c[1][b*H + j] = cn;
        float hn = sigm(go)*tanhf(cn);
        g_h1[b*H + j] = hn;
        sh1[j] = hn;
    }
    __syncthreads();

    for (int n0 = warp; n0 < H; n0 += 8) {
        const float* wr = g_WaT + (size_t)n0*H;
        float a = 0.f;
#pragma unroll
        for (int kk = 0; kk < 4; kk++) {
            int k = kk*128 + lane*4;
            float4 w  = *reinterpret_cast<const float4*>(wr + k);
            float4 hx = *reinterpret_cast<const float4*>(sh1 + k);
            a += w.x*hx.x + w.y*hx.y + w.z*hx.z + w.w*hx.w;
        }
#pragma unroll
        for (int off = 16; off; off >>= 1) a += __shfl_xor_sync(0xffffffffu, a, off);
        if (lane == 0) sq[n0] = a;
    }
    __syncthreads();

    for (int s0 = warp; s0 < S; s0 += 8) {
        const float* m = mb + ((size_t)s0*B + b)*H;
        float a = 0.f;
#pragma unroll
        for (int kk = 0; kk < 4; kk++) {
            int k = kk*128 + lane*4;
            float4 mv = *reinterpret_cast<const float4*>(m + k);
            float4 qv = *reinterpret_cast<const float4*>(sq + k);
            a += mv.x*qv.x + mv.y*qv.y + mv.z*qv.z + mv.w*qv.w;
        }
#pragma unroll
        for (int off = 16; off; off >>= 1) a += __shfl_xor_sync(0xffffffffu, a, off);
        if (lane == 0) al[s0] = (s0 < len) ? a : -1.0e9f;
    }
    __syncthreads();

    float v = al[tid];
    red[tid] = v; __syncthreads();
    for (int o = 128; o; o >>= 1) { if (tid < o) red[tid] = fmaxf(red[tid], red[tid+o]); __syncthreads(); }
    float vmax = red[0];
    __syncthreads();
    float e = expf(v - vmax);
    red[tid] = e; __syncthreads();
    for (int o = 128; o; o >>= 1) { if (tid < o) red[tid] += red[tid+o]; __syncthreads(); }
    float p = e / red[0];
    al[tid] = p;
    attn_out[((size_t)t*B + b)*S + tid] = p;
    __syncthreads();

    for (int k = tid; k < H; k += 256) {
        float acc = 0.f;
#pragma unroll 4
        for (int s = 0; s < S; s++) acc += al[s] * mb[((size_t)s*B + b)*H + k];
        sctx[k] = acc;
    }
    __syncthreads();

    // fused Wc: warp per output row n (proven in R14 Phase D)
    for (int n = warp; n < H; n += 8) {
        const float* wr = Wc + (size_t)n*1024;
        float a = 0.f;
#pragma unroll
        for (int kk = 0; kk < 4; kk++) {
            int k = kk*128 + lane*4;
            float4 w  = *reinterpret_cast<const float4*>(wr + k);
            float4 cx = *reinterpret_cast<const float4*>(sctx + k);
            a += w.x*cx.x + w.y*cx.y + w.z*cx.z + w.w*cx.w;
            float4 w2 = *reinterpret_cast<const float4*>(wr + 512 + k);
            float4 hx = *reinterpret_cast<const float4*>(sh1 + k);
            a += w2.x*hx.x + w2.y*hx.y + w2.z*hx.z + w2.w*hx.w;
        }
#pragma unroll
        for (int off = 16; off; off >>= 1) a += __shfl_xor_sync(0xffffffffu, a, off);
        if (lane == 0) {
            float d = tanhf(a);
            g_dec[b*H + n] = d;
            scatter_frag(g_xq, b, n, d);
        }
    }
}

__global__ void __launch_bounds__(256) k_lsm(float* __restrict__ out) {
    __shared__ float lz;
    const int t = blockIdx.z, b = blockIdx.y;
    if (threadIdx.x == 0) lz = logf(g_sumZ[t*B + b]);
    __syncthreads();
    int v = blockIdx.x*256 + threadIdx.x;
    out[((size_t)(t*B + b))*V + v] -= lz;
}

// ------------------------- launch -------------------------------------------
extern "C" void kernel_launch(void* const* d_in, const int* in_sizes, int n_in,
                              void* d_out, int out_size) {
    const int*   tgt   = (const int*)  d_in[0];
    const float* mb    = (const float*)d_in[1];
    const int*   mlen  = (const int*)  d_in[2];
    const float* enc_h = (const float*)d_in[3];
    const float* enc_c = (const float*)d_in[4];
    const float* emb   = (const float*)d_in[5];
    const float* Wx0   = (const float*)d_in[6];
    const float* Wh0   = (const float*)d_in[7];
    const float* b0    = (const float*)d_in[8];
    const float* Wx1   = (const float*)d_in[9];
    const float* Wh1   = (const float*)d_in[10];
    const float* b1    = (const float*)d_in[11];
    const float* Wa    = (const float*)d_in[12];
    const float* Wc    = (const float*)d_in[13];
    const float* Wgen  = (const float*)d_in[14];
    const float* bgen  = (const float*)d_in[15];

    float* out      = (float*)d_out;
    float* attn_out = out + (size_t)TS*B*V;

    k_init <<<(H*H + 255)/256, 256>>>(enc_h, enc_c, Wa);
    k_embed<<<(TS*B*H)/256, 256>>>(tgt, emb);
    k_pack <<<NG*32, 256>>>(Wgen);

    for (int t = 0; t < TS; t++) {
        k_mix <<<MIXB, 256>>>(Wx0, Wh0, Wh1, Wx1, b0, bgen, out, t, t - 1);
        k_attn<<<B, 256>>>(mb, mlen, b1, Wc, attn_out, t);
    }
    // final generator (t = TS-1): gen blocks only
    k_mix<<<GENB, 256>>>(Wx0, Wh0, Wh1, Wx1, b0, bgen, out, 0, TS - 1);
    k_lsm<<<dim3(V/256, B, TS), 256>>>(out);
}

// round 17
// speedup vs baseline: 2.6437x; 2.2888x over previous
#include <cuda_runtime.h>
#include <cuda_bf16.h>
#include <cstdint>
#include <math.h>

#define TS 63
#define B 32
#define S 256
#define H 512
#define V 32000
#define NG (V/16)              /* 2000 gen A-row groups */
#define KC (H/16)              /* 32 bf16 k-chunks */
#define XFRAG (4*KC*32*4)      /* bf16 X image: uint32 count */
#define GENB 250               /* V/128 generator tiles */
#define GATEB 1024

// ------------------------- device scratch -----------------------------------
__device__ float g_h0[B*H];
__device__ float g_h1[B*H];
__device__ float g_c[2][B*H];
__device__ float g_emb[TS][B*H];
__device__ float g_dec[B*H];
__device__ float g_part0[3][2048*B];
__device__ float g_part1[2][2048*B];
__device__ float g_WaT[H*H];
__device__ float g_sumZ[TS*B];
__device__ __align__(16) uint32_t g_Wq[(size_t)NG*KC*32*8];
__device__ __align__(16) uint32_t g_xq[XFRAG];

// ------------------------- helpers -------------------------------------------
__device__ __forceinline__ void mma16816(float c[4], const uint32_t a[4],
                                         uint32_t b0, uint32_t b1) {
    asm volatile("mma.sync.aligned.m16n8k16.row.col.f32.bf16.bf16.f32 "
        "{%0,%1,%2,%3}, {%4,%5,%6,%7}, {%8,%9}, {%0,%1,%2,%3};"
        : "+f"(c[0]), "+f"(c[1]), "+f"(c[2]), "+f"(c[3])
        : "r"(a[0]), "r"(a[1]), "r"(a[2]), "r"(a[3]), "r"(b0), "r"(b1));
}
__device__ __forceinline__ uint32_t pack_bf16(float x, float y) {
    __nv_bfloat162 v = __floats2bfloat162_rn(x, y);
    return *reinterpret_cast<uint32_t*>(&v);
}
__device__ __forceinline__ float bf16_hi_f(float x) {
    __nv_bfloat16 h = __float2bfloat16_rn(x);
    return __bfloat162float(h);
}
__device__ __forceinline__ void scatter_frag(uint32_t* base, int b, int k, float v) {
    int bg = b >> 3, gid = b & 7;
    int c = k >> 4, kk = k & 15;
    int hi8 = kk >> 3, tig = (kk >> 1) & 3, half = kk & 1;
    int lane = gid*4 + tig;
    int idx2 = (bg*KC + c)*32 + lane;
    __nv_bfloat16 hb = __float2bfloat16_rn(v);
    float hv = __bfloat162float(hb);
    __nv_bfloat16 lb = __float2bfloat16_rn(v - hv);
    unsigned short* p16 = reinterpret_cast<unsigned short*>(base);
    p16[(idx2*4 + hi8)*2 + half]     = *reinterpret_cast<unsigned short*>(&hb);
    p16[(idx2*4 + 2 + hi8)*2 + half] = *reinterpret_cast<unsigned short*>(&lb);
}
__device__ __forceinline__ float sigm(float x) { return 1.f/(1.f+expf(-x)); }

// ------------------------- warp GEMV (proven) ---------------------------------
__device__ __forceinline__ void warp_gemv_acc(const float* __restrict__ Wrow,
                                              const float* __restrict__ X,
                                              float acc[B]) {
    const int lane = threadIdx.x & 31;
#pragma unroll
    for (int kk = 0; kk < 4; kk++) {
        const int k = kk*128 + lane*4;
        const float4 w = *reinterpret_cast<const float4*>(Wrow + k);
#pragma unroll
        for (int b = 0; b < B; b++) {
            const float4 x = *reinterpret_cast<const float4*>(X + b*H + k);
            acc[b] += w.x*x.x + w.y*x.y + w.z*x.z + w.w*x.w;
        }
    }
}
__device__ __forceinline__ float warp_reduce_b(float acc[B], float* sm) {
    const int lane = threadIdx.x & 31;
#pragma unroll
    for (int b = 0; b < B; b++) sm[b*33 + lane] = acc[b];
    __syncwarp();
    float s = 0.f;
#pragma unroll
    for (int j = 0; j < 32; j++) s += sm[lane*33 + j];
    return s;
}

// ------------------------- shared union for k_mix ------------------------------
union MixSmem {
    float gemv[8][33*32];   // 33792 B
    float Dsm[128*33];      // 16896 B
};

// ------------------------- generator tile (bf16x3, proven) --------------------
__device__ void gen_tile(int tile, int tGen, const float* __restrict__ bgen,
                         float* __restrict__ out, float* Dsm) {
    const int tid = threadIdx.x;
    const int wid = tid >> 5, lane = tid & 31;
    const int gid = lane >> 2, tig = lane & 3;
    const int nt = tile * 128;
    const int ngrp = tile*8 + wid;
    const uint32_t* wq = g_Wq + (size_t)ngrp*KC*32*8;

    float acc[4][4] = {};
    for (int c = 0; c < KC; c++) {
        const uint32_t* ap = wq + (c*32 + lane)*8;
        uint4 ahiv = *reinterpret_cast<const uint4*>(ap);
        uint4 alov = *reinterpret_cast<const uint4*>(ap + 4);
        uint32_t ahi[4] = {ahiv.x, ahiv.y, ahiv.z, ahiv.w};
        uint32_t alo[4] = {alov.x, alov.y, alov.z, alov.w};
#pragma unroll
        for (int bg = 0; bg < 4; bg++) {
            uint4 xb = *reinterpret_cast<const uint4*>(&g_xq[((bg*KC + c)*32 + lane)*4]);
            mma16816(acc[bg], ahi, xb.x, xb.y);
            mma16816(acc[bg], ahi, xb.z, xb.w);
            mma16816(acc[bg], alo, xb.x, xb.y);
        }
    }
#pragma unroll
    for (int bg = 0; bg < 4; bg++) {
#pragma unroll
        for (int r = 0; r < 4; r++) {
            int nl = wid*16 + gid + ((r >= 2) ? 8 : 0);
            int b  = bg*8 + tig*2 + (r & 1);
            Dsm[nl*33 + b] = acc[bg][r];
        }
    }
    __syncthreads();

    const int n = tid & 127, bh = tid >> 7;
    const float bias = bgen[nt + n];
    float* obase = out + (size_t)tGen*B*V + nt + n;
#pragma unroll
    for (int j = 0; j < 16; j++) {
        int b = bh*16 + j;
        float v = Dsm[n*33 + b] + bias;
        obase[(size_t)b*V] = v;
        Dsm[n*33 + b] = expf(v);
    }
    __syncthreads();
    if (tid < 32) {
        float s = 0.f;
#pragma unroll 8
        for (int nn = 0; nn < 128; nn++) s += Dsm[nn*33 + tid];
        atomicAdd(&g_sumZ[tGen*B + tid], s);
    }
}

// ------------------------- prologue kernels -----------------------------------
__global__ void __launch_bounds__(256) k_init(const float* __restrict__ eh,
                                              const float* __restrict__ ec,
                                              const float* __restrict__ Wa) {
    int idx = blockIdx.x*256 + threadIdx.x;           // grid covers H*H
    if (idx < 2*B*H) {
        (&g_c[0][0])[idx] = ec[idx];
        int layer = idx >> 14;
        int rem = idx & (B*H - 1);
        if (layer == 0) g_h0[rem] = eh[idx];
        else            g_h1[rem] = eh[idx];
    }
    if (idx < B*H)   g_dec[idx] = 0.f;
    if (idx < TS*B)  g_sumZ[idx] = 0.f;
    if (idx < H*H)   { int h = idx / H; int k = idx - h*H; g_WaT[k*H + h] = Wa[idx]; }
}

__global__ void __launch_bounds__(256) k_embed(const int* __restrict__ tgt,
                                               const float* __restrict__ et) {
    int idx = blockIdx.x*256 + threadIdx.x;           // < TS*B*H
    int e = idx & (H - 1);
    int r = idx >> 9;
    int tok = tgt[r];
    (&g_emb[0][0])[idx] = et[(size_t)tok*H + e];
}

__global__ void __launch_bounds__(256) k_pack(const float* __restrict__ Wgen) {
    int idx = blockIdx.x*256 + threadIdx.x;           // < NG*KC*32*8
    int reg  = idx & 7;
    int lane = (idx >> 3) & 31;
    int c    = (idx >> 8) & 31;
    int g    = idx >> 13;
    int split = reg >> 2, r4 = reg & 3;
    int gid = lane >> 2, tig = lane & 3;
    int n = g*16 + gid + ((r4 & 1) ? 8 : 0);
    int k = c*16 + tig*2 + ((r4 & 2) ? 8 : 0);
    float w0 = Wgen[(size_t)n*H + k];
    float w1 = Wgen[(size_t)n*H + k + 1];
    float h0 = bf16_hi_f(w0), h1 = bf16_hi_f(w1);
    g_Wq[idx] = (split == 0) ? pack_bf16(h0, h1) : pack_bf16(w0 - h0, w1 - h1);
}

// ------------------------- k_mix: gen(t-1) + 4 gate GEMVs (R11, proven) -------
__global__ void __launch_bounds__(256) k_mix(const float* __restrict__ Wx0,
                                             const float* __restrict__ Wh0,
                                             const float* __restrict__ Wh1,
                                             const float* __restrict__ bgen,
                                             float* __restrict__ out,
                                             int t, int tGen) {
    __shared__ MixSmem u;
    if ((int)blockIdx.x < GENB) {
        if (tGen >= 0) gen_tile(blockIdx.x, tGen, bgen, out, u.Dsm);
        return;
    }
    const int blk = blockIdx.x - GENB;                // 0..1023
    const int p = blk >> 8, nb = blk & 255;
    const int warp = threadIdx.x >> 5, lane = threadIdx.x & 31;
    const int n = nb*8 + warp;                        // 0..2047
    const float* Wrow; const float* X; float* dst;
    if (p == 0)      { Wrow = Wx0 + (size_t)n*1024;       X = g_emb[t]; dst = &g_part0[0][0]; }
    else if (p == 1) { Wrow = Wx0 + (size_t)n*1024 + 512; X = g_dec;    dst = &g_part0[1][0]; }
    else if (p == 2) { Wrow = Wh0 + (size_t)n*512;        X = g_h0;     dst = &g_part0[2][0]; }
    else             { Wrow = Wh1 + (size_t)n*512;        X = g_h1;     dst = &g_part1[1][0]; }
    float acc[B] = {};
    warp_gemv_acc(Wrow, X, acc);
    float s = warp_reduce_b(acc, u.gemv[warp]);
    dst[n*B + lane] = s;
}

// Wx1 x h0 (needs act0 output) -> part1[0] (R11, proven)
__global__ void __launch_bounds__(256) k_g1p0(const float* __restrict__ Wx1) {
    __shared__ float sm[8][33*32];
    const int warp = threadIdx.x >> 5, lane = threadIdx.x & 31;
    const int n = blockIdx.x*8 + warp;
    float acc[B] = {};
    warp_gemv_acc(Wx1 + (size_t)n*512, g_h0, acc);
    float s = warp_reduce_b(acc, sm[warp]);
    g_part1[0][n*B + lane] = s;
}

// Layer-0 activation (R11, proven)
__global__ void __launch_bounds__(256) k_act0(const float* __restrict__ bias) {
    int idx = blockIdx.x*256 + threadIdx.x;
    int b = idx & 31, j = idx >> 5;
    float gi = bias[j], gf = bias[512+j], gg = bias[1024+j], go = bias[1536+j];
#pragma unroll
    for (int p = 0; p < 3; p++) {
        const float* pp = &g_part0[p][0];
        gi += pp[(j       )*B + b];
        gf += pp[(512 + j )*B + b];
        gg += pp[(1024 + j)*B + b];
        go += pp[(1536 + j)*B + b];
    }
    float c  = g_c[0][b*H + j];
    float cn = sigm(gf)*c + sigm(gi)*tanhf(gg);
    g_c[0][b*H + j] = cn;
    g_h0[b*H + j] = sigm(go)*tanhf(cn);
}

// ------------------------- k_attn: 1024 threads, fully fused ------------------
// act1 + q + align + softmax + ctx + Wc(tanh) + dec/frag scatter, per batch b.
__global__ void __launch_bounds__(1024) k_attn(const float* __restrict__ mb,
                                               const int* __restrict__ mlen,
                                               const float* __restrict__ b1v,
                                               const float* __restrict__ Wc,
                                               float* __restrict__ attn_out, int t) {
    __shared__ float sh1[H];
    __shared__ float sq[H];
    __shared__ float al[S];
    __shared__ float red[256];
    __shared__ float sctx[H];
    __shared__ float sctxh[1024];
    const int b = blockIdx.x;
    const int tid = threadIdx.x, warp = tid >> 5, lane = tid & 31;
    const int len = mlen[b];

    // ---- act1 (512 threads active) ----
    if (tid < H) {
        const int j = tid;
        float gi = b1v[j], gf = b1v[512+j], gg = b1v[1024+j], go = b1v[1536+j];
#pragma unroll
        for (int p = 0; p < 2; p++) {
            const float* pp = &g_part1[p][0];
            gi += pp[(j       )*B + b];
            gf += pp[(512 + j )*B + b];
            gg += pp[(1024 + j)*B + b];
            go += pp[(1536 + j)*B + b];
        }
        float c  = g_c[1][b*H + j];
        float cn = sigm(gf)*c + sigm(gi)*tanhf(gg);
        g_c[1][b*H + j] = cn;
        float hn = sigm(go)*tanhf(cn);
        g_h1[b*H + j] = hn;
        sh1[j] = hn;
    }
    __syncthreads();

    // ---- q: 32 warps x 16 rows each ----
    for (int n0 = warp; n0 < H; n0 += 32) {
        const float* wr = g_WaT + (size_t)n0*H;
        float a = 0.f;
#pragma unroll
        for (int kk = 0; kk < 4; kk++) {
            int k = kk*128 + lane*4;
            float4 w  = *reinterpret_cast<const float4*>(wr + k);
            float4 hx = *reinterpret_cast<const float4*>(sh1 + k);
            a += w.x*hx.x + w.y*hx.y + w.z*hx.z + w.w*hx.w;
        }
#pragma unroll
        for (int off = 16; off; off >>= 1) a += __shfl_xor_sync(0xffffffffu, a, off);
        if (lane == 0) sq[n0] = a;
    }
    __syncthreads();

    // ---- align: 32 warps x 8 s-rows each ----
    for (int s0 = warp; s0 < S; s0 += 32) {
        const float* m = mb + ((size_t)s0*B + b)*H;
        float a = 0.f;
#pragma unroll
        for (int kk = 0; kk < 4; kk++) {
            int k = kk*128 + lane*4;
            float4 mv = *reinterpret_cast<const float4*>(m + k);
            float4 qv = *reinterpret_cast<const float4*>(sq + k);
            a += mv.x*qv.x + mv.y*qv.y + mv.z*qv.z + mv.w*qv.w;
        }
#pragma unroll
        for (int off = 16; off; off >>= 1) a += __shfl_xor_sync(0xffffffffu, a, off);
        if (lane == 0) al[s0] = (s0 < len) ? a : -1.0e9f;
    }
    __syncthreads();

    // ---- softmax over S=256 (first 256 threads carry data; all sync) ----
    float v = 0.f;
    if (tid < 256) { v = al[tid]; red[tid] = v; }
    __syncthreads();
    for (int o = 128; o; o >>= 1) {
        if (tid < o) red[tid] = fmaxf(red[tid], red[tid + o]);
        __syncthreads();
    }
    float vmax = red[0];
    __syncthreads();
    float e = 0.f;
    if (tid < 256) { e = expf(v - vmax); red[tid] = e; }
    __syncthreads();
    for (int o = 128; o; o >>= 1) {
        if (tid < o) red[tid] += red[tid + o];
        __syncthreads();
    }
    if (tid < 256) {
        float p = e / red[0];
        al[tid] = p;
        attn_out[((size_t)t*B + b)*S + tid] = p;
    }
    __syncthreads();

    // ---- ctx: 2 threads per k (s split 128+128), 4 accumulators each ----
    {
        const int k = tid >> 1, sh = tid & 1;
        const float* mcol = mb + (size_t)b*H + k + (size_t)(sh*128)*B*H;
        const float* pv = al + sh*128;
        float a0 = 0.f, a1 = 0.f, a2 = 0.f, a3 = 0.f;
#pragma unroll 8
        for (int s = 0; s < 128; s += 4) {
            a0 += pv[s+0] * mcol[(size_t)(s+0)*B*H];
            a1 += pv[s+1] * mcol[(size_t)(s+1)*B*H];
            a2 += pv[s+2] * mcol[(size_t)(s+2)*B*H];
            a3 += pv[s+3] * mcol[(size_t)(s+3)*B*H];
        }
        sctxh[tid] = (a0 + a1) + (a2 + a3);
    }
    __syncthreads();
    if (tid < H) sctx[tid] = sctxh[2*tid] + sctxh[2*tid + 1];
    __syncthreads();

    // ---- fused Wc: 32 warps x 16 rows each ----
    for (int n = warp; n < H; n += 32) {
        const float* wr = Wc + (size_t)n*1024;
        float a = 0.f;
#pragma unroll
        for (int kk = 0; kk < 4; kk++) {
            int k = kk*128 + lane*4;
            float4 w  = *reinterpret_cast<const float4*>(wr + k);
            float4 cx = *reinterpret_cast<const float4*>(sctx + k);
            a += w.x*cx.x + w.y*cx.y + w.z*cx.z + w.w*cx.w;
            float4 w2 = *reinterpret_cast<const float4*>(wr + 512 + k);
            float4 hx = *reinterpret_cast<const float4*>(sh1 + k);
            a += w2.x*hx.x + w2.y*hx.y + w2.z*hx.z + w2.w*hx.w;
        }
#pragma unroll
        for (int off = 16; off; off >>= 1) a += __shfl_xor_sync(0xffffffffu, a, off);
        if (lane == 0) {
            float d = tanhf(a);
            g_dec[b*H + n] = d;
            scatter_frag(g_xq, b, n, d);
        }
    }
}

__global__ void __launch_bounds__(256) k_lsm(float* __restrict__ out) {
    __shared__ float lz;
    const int t = blockIdx.z, b = blockIdx.y;
    if (threadIdx.x == 0) lz = logf(g_sumZ[t*B + b]);
    __syncthreads();
    int v = blockIdx.x*256 + threadIdx.x;
    out[((size_t)(t*B + b))*V + v] -= lz;
}

// ------------------------- launch -------------------------------------------
extern "C" void kernel_launch(void* const* d_in, const int* in_sizes, int n_in,
                              void* d_out, int out_size) {
    const int*   tgt   = (const int*)  d_in[0];
    const float* mb    = (const float*)d_in[1];
    const int*   mlen  = (const int*)  d_in[2];
    const float* enc_h = (const float*)d_in[3];
    const float* enc_c = (const float*)d_in[4];
    const float* emb   = (const float*)d_in[5];
    const float* Wx0   = (const float*)d_in[6];
    const float* Wh0   = (const float*)d_in[7];
    const float* b0    = (const float*)d_in[8];
    const float* Wx1   = (const float*)d_in[9];
    const float* Wh1   = (const float*)d_in[10];
    const float* b1    = (const float*)d_in[11];
    const float* Wa    = (const float*)d_in[12];
    const float* Wc    = (const float*)d_in[13];
    const float* Wgen  = (const float*)d_in[14];
    const float* bgen  = (const float*)d_in[15];

    float* out      = (float*)d_out;
    float* attn_out = out + (size_t)TS*B*V;

    k_init <<<(H*H + 255)/256, 256>>>(enc_h, enc_c, Wa);
    k_embed<<<(TS*B*H)/256, 256>>>(tgt, emb);
    k_pack <<<NG*32, 256>>>(Wgen);

    for (int t = 0; t < TS; t++) {
        k_mix <<<GENB + GATEB, 256>>>(Wx0, Wh0, Wh1, bgen, out, t, t - 1);
        k_act0<<<(B*H)/256, 256>>>(b0);
        k_g1p0<<<2048/8, 256>>>(Wx1);
        k_attn<<<B, 1024>>>(mb, mlen, b1, Wc, attn_out, t);
    }
    k_mix<<<GENB, 256>>>(Wx0, Wh0, Wh1, bgen, out, 0, TS - 1);
    k_lsm<<<dim3(V/256, B, TS), 256>>>(out);
}